// round 4
// baseline (speedup 1.0000x reference)
#include <cuda_runtime.h>
#include <cuda_bf16.h>

// PCEN via exact parallel linear-recurrence scan (constant per-row decay a=1-s).
// R4: same as R3 but transcendentals pinned to MUFU via inline PTX
// (lg2/ex2/rsq.approx), independent of harness fast-math flags.
// Uniform init trick: m[-1]=x0 seeds the level-3 scan, no per-element SELs.

#define TT    8000
#define EPT   8
#define NTH   1024
#define NWARP (NTH/32)
#define ALPHA_C 0.98f
#define DELTA_C 2.0f
#define EPS_C   1e-6f
#define SQRT_DELTA 1.41421356237f

__device__ __forceinline__ float f_lg2(float x) {
    float r; asm("lg2.approx.f32 %0, %1;" : "=f"(r) : "f"(x)); return r;
}
__device__ __forceinline__ float f_ex2(float x) {
    float r; asm("ex2.approx.f32 %0, %1;" : "=f"(r) : "f"(x)); return r;
}
__device__ __forceinline__ float f_rsq(float x) {
    float r; asm("rsqrt.approx.f32 %0, %1;" : "=f"(r) : "f"(x)); return r;
}

__global__ __launch_bounds__(NTH, 2)
void pcen_kernel(const float* __restrict__ x,
                 const float* __restrict__ log_s,
                 float* __restrict__ out,
                 int F)
{
    const int row = blockIdx.x;
    const int f   = row % F;
    const float s = f_ex2(1.44269504089f * __ldg(log_s + f));  // exp(log_s)
    const float a = 1.0f - s;

    const float* xr   = x   + (long long)row * TT;
    float*       orow = out + (long long)row * TT;

    const int t    = threadIdx.x;
    const int base = t * EPT;
    const bool active = (base < TT);          // threads 0..999 carry data

    __shared__ float warpTot[NWARP];
    __shared__ float warpPre[NWARP];
    __shared__ float x0sh;

    // ---- load 8 contiguous elements (2x LDG.128) ----
    float xv[EPT];
    if (active) {
        const float4* p = (const float4*)(xr + base);
        float4 v0 = p[0];
        float4 v1 = p[1];
        xv[0]=v0.x; xv[1]=v0.y; xv[2]=v0.z; xv[3]=v0.w;
        xv[4]=v1.x; xv[5]=v1.y; xv[6]=v1.z; xv[7]=v1.w;
    } else {
        #pragma unroll
        for (int i = 0; i < EPT; i++) xv[i] = 0.0f;
    }
    if (t == 0) x0sh = xv[0];   // virtual initial state m[-1] = x[0]

    // ---- pass 1: zero-init local scan -> segment total (uniform weights) ----
    float Fv = 0.0f;
    #pragma unroll
    for (int i = 0; i < EPT; i++)
        Fv = fmaf(a, Fv, s * xv[i]);
    if (!active) Fv = 0.0f;

    // D = a^EPT
    float D = a;
    #pragma unroll
    for (int k = 0; k < 3; k++) D = D * D;    // a^8

    const int lane = t & 31;
    const int wid  = t >> 5;

    // ---- level 2: Hillis-Steele warp scan with decay ----
    float val = Fv;
    float pw  = D;        // D^(2^k)
    float pl  = 1.0f;     // D^lane
    #pragma unroll
    for (int off = 1; off < 32; off <<= 1) {
        float up = __shfl_up_sync(0xFFFFFFFFu, val, off);
        if (lane & off) pl *= pw;
        if (lane >= off) val = fmaf(pw, up, val);
        pw = pw * pw;
    }
    const float Dw = pw;  // D^32 = a^256

    if (lane == 31) warpTot[wid] = val;
    __syncthreads();

    // ---- level 3: warp 0 scans warp totals, seeded with m[-1] = x0 ----
    if (wid == 0) {
        const float x0 = x0sh;
        float v   = warpTot[lane];
        float w2  = Dw;
        float plw = 1.0f;     // Dw^lane
        #pragma unroll
        for (int off = 1; off < 32; off <<= 1) {
            float up = __shfl_up_sync(0xFFFFFFFFu, v, off);
            if (lane & off) plw *= w2;
            if (lane >= off) v = fmaf(w2, up, v);
            w2 = w2 * w2;
        }
        float ex = __shfl_up_sync(0xFFFFFFFFu, v, 1);
        if (lane == 0) ex = 0.0f;
        // state entering warp `lane` = Dw^lane * x0 + exclusive-scan
        warpPre[lane] = fmaf(plw, x0, ex);
    }
    __syncthreads();

    // exclusive within-warp
    float vex = __shfl_up_sync(0xFFFFFFFFu, val, 1);
    if (lane == 0) vex = 0.0f;

    // state entering this thread's segment
    const float carry = fmaf(pl, warpPre[wid], vex);

    // ---- pass 2: replay with true carry, emit output ----
    if (active) {
        float m = carry;
        float ov[EPT];
        #pragma unroll
        for (int i = 0; i < EPT; i++) {
            m = fmaf(a, m, s * xv[i]);
            // (x * (eps+m)^-alpha + delta)^0.5 - delta^0.5
            float l   = f_lg2(EPS_C + m);             // MUFU.LG2
            float inv = f_ex2(-ALPHA_C * l);          // MUFU.EX2
            float u   = fmaf(xv[i], inv, DELTA_C);    // u >= DELTA > 0
            ov[i] = u * f_rsq(u) - SQRT_DELTA;        // MUFU.RSQ + FMUL
        }
        float4* po = (float4*)(orow + base);
        po[0] = make_float4(ov[0], ov[1], ov[2], ov[3]);
        po[1] = make_float4(ov[4], ov[5], ov[6], ov[7]);
    }
}

extern "C" void kernel_launch(void* const* d_in, const int* in_sizes, int n_in,
                              void* d_out, int out_size)
{
    int xi = 0, si = 1;
    if (n_in >= 2 && in_sizes[0] < in_sizes[1]) { xi = 1; si = 0; }

    const float* x     = (const float*)d_in[xi];
    const float* log_s = (const float*)d_in[si];
    float*       out   = (float*)d_out;

    const int F    = in_sizes[si];           // 128
    const int rows = in_sizes[xi] / TT;      // B*F = 4096

    pcen_kernel<<<rows, NTH>>>(x, log_s, out, F);
}

// round 5
// speedup vs baseline: 1.0058x; 1.0058x over previous
#include <cuda_runtime.h>
#include <cuda_bf16.h>

// PCEN via exact parallel linear-recurrence scan (constant per-row decay a=1-s).
// R5: single-barrier version. Every warp redundantly scans the 32 warp totals
// (no serial warp0 section, one __syncthreads instead of two). Lane powers of
// the decay via ex2(lane*lg2(D)) instead of predicated multiply chains.
// Epilogue: lg2/ex2 pow + sqrt.approx, output transformed in place.

#define TT    8000
#define EPT   8
#define NTH   1024
#define NWARP (NTH/32)
#define ALPHA_C 0.98f
#define DELTA_C 2.0f
#define EPS_C   1e-6f
#define SQRT_DELTA 1.41421356237f
#define LOG2E 1.44269504089f

__device__ __forceinline__ float f_lg2(float x) {
    float r; asm("lg2.approx.f32 %0, %1;" : "=f"(r) : "f"(x)); return r;
}
__device__ __forceinline__ float f_ex2(float x) {
    float r; asm("ex2.approx.f32 %0, %1;" : "=f"(r) : "f"(x)); return r;
}
__device__ __forceinline__ float f_sqrt(float x) {
    float r; asm("sqrt.approx.f32 %0, %1;" : "=f"(r) : "f"(x)); return r;
}

__global__ __launch_bounds__(NTH, 2)
void pcen_kernel(const float* __restrict__ x,
                 const float* __restrict__ log_s,
                 float* __restrict__ out,
                 int F)
{
    const int row = blockIdx.x;
    const int f   = row % F;
    const float s = f_ex2(LOG2E * __ldg(log_s + f));   // exp(log_s)
    const float a = 1.0f - s;

    const float* xr   = x   + (long long)row * TT;
    float*       orow = out + (long long)row * TT;

    const int t    = threadIdx.x;
    const int base = t * EPT;
    const bool active = (base < TT);          // threads 0..999 carry data
    const int lane = t & 31;
    const int wid  = t >> 5;

    __shared__ float warpTot[NWARP];
    __shared__ float x0sh;

    // decay powers: D = a^8 (exact squarings), lane powers via MUFU
    const float lga  = f_lg2(a);              // log2(a)
    const float lgD  = 8.0f  * lga;           // log2(a^8)
    const float lgDw = 256.0f * lga;          // log2(a^256)

    // ---- load 8 contiguous elements (2x LDG.128) ----
    float xv[EPT];
    if (active) {
        const float4* p = (const float4*)(xr + base);
        float4 v0 = p[0];
        float4 v1 = p[1];
        xv[0]=v0.x; xv[1]=v0.y; xv[2]=v0.z; xv[3]=v0.w;
        xv[4]=v1.x; xv[5]=v1.y; xv[6]=v1.z; xv[7]=v1.w;
    } else {
        #pragma unroll
        for (int i = 0; i < EPT; i++) xv[i] = 0.0f;
    }
    if (t == 0) x0sh = xv[0];   // virtual initial state m[-1] = x[0]

    // ---- pass 1: zero-init local scan -> segment total ----
    float Fv = 0.0f;
    #pragma unroll
    for (int i = 0; i < EPT; i++)
        Fv = fmaf(a, Fv, s * xv[i]);          // inactive threads: xv=0 -> Fv=0

    float D = a; D = D*D; D = D*D; D = D*D;   // a^8 exact

    // ---- level 2: Hillis-Steele warp scan with decay ----
    float val = Fv;
    float pw  = D;                            // D^(2^k)
    #pragma unroll
    for (int off = 1; off < 32; off <<= 1) {
        float up = __shfl_up_sync(0xFFFFFFFFu, val, off);
        if (lane >= off) val = fmaf(pw, up, val);
        pw = pw * pw;
    }
    const float Dw = pw;                      // D^32 = a^256

    if (lane == 31) warpTot[wid] = val;

    // exclusive-within-warp value (independent of barrier)
    float vex = __shfl_up_sync(0xFFFFFFFFu, val, 1);
    if (lane == 0) vex = 0.0f;
    const float pl = f_ex2((float)lane * lgD);   // D^lane

    __syncthreads();

    // ---- level 3: EVERY warp redundantly scans the 32 warp totals ----
    float v  = warpTot[lane];
    float w2 = Dw;
    #pragma unroll
    for (int off = 1; off < 32; off <<= 1) {
        float up = __shfl_up_sync(0xFFFFFFFFu, v, off);
        if (lane >= off) v = fmaf(w2, up, v);
        w2 = w2 * w2;
    }
    // exclusive level-3 prefix for *this* warp: value at lane wid-1 (0 if wid==0)
    float ex = __shfl_sync(0xFFFFFFFFu, v, (wid == 0) ? 0 : (wid - 1));
    if (wid == 0) ex = 0.0f;
    const float plw  = f_ex2((float)wid * lgDw);     // Dw^wid (underflow->0 ok)
    const float wpre = fmaf(plw, x0sh, ex);          // state entering this warp

    // state entering this thread's segment
    const float carry = fmaf(pl, wpre, vex);

    // ---- pass 2: replay with true carry, transform in place, store ----
    if (active) {
        float m = carry;
        #pragma unroll
        for (int i = 0; i < EPT; i++) {
            m = fmaf(a, m, s * xv[i]);
            float l   = f_lg2(EPS_C + m);            // MUFU.LG2
            float inv = f_ex2(-ALPHA_C * l);         // MUFU.EX2
            float u   = fmaf(xv[i], inv, DELTA_C);   // u >= DELTA > 0
            xv[i] = f_sqrt(u) - SQRT_DELTA;          // MUFU.SQRT
        }
        float4* po = (float4*)(orow + base);
        po[0] = make_float4(xv[0], xv[1], xv[2], xv[3]);
        po[1] = make_float4(xv[4], xv[5], xv[6], xv[7]);
    }
}

extern "C" void kernel_launch(void* const* d_in, const int* in_sizes, int n_in,
                              void* d_out, int out_size)
{
    int xi = 0, si = 1;
    if (n_in >= 2 && in_sizes[0] < in_sizes[1]) { xi = 1; si = 0; }

    const float* x     = (const float*)d_in[xi];
    const float* log_s = (const float*)d_in[si];
    float*       out   = (float*)d_out;

    const int F    = in_sizes[si];           // 128
    const int rows = in_sizes[xi] / TT;      // B*F = 4096

    pcen_kernel<<<rows, NTH>>>(x, log_s, out, F);
}